// round 15
// baseline (speedup 1.0000x reference)
#include <cuda_runtime.h>
#include <cuda_fp16.h>
#include <cstdint>
#include <cmath>

// ---------------------------------------------------------------------------
// Problem dims (fixed)
#define B_DIM 8
#define L_DIM 4096
#define D_DIM 512
#define M_DIM (B_DIM * L_DIM)   // 32768
#define N1 (2 * D_DIM)          // 1024
#define K1 (D_DIM)              // 512
#define N2 (D_DIM)              // 512
#define K2 (2 * D_DIM)          // 1024

#define CHUNK 256
#define NCHUNK (L_DIM / CHUNK)  // 16

// Scratch (device globals; allocation is banned)
__device__ __align__(1024) __half g_inh[(size_t)M_DIM * K1];    // 32 MB  half inputs
__device__ __align__(1024) __half g_uh[(size_t)M_DIM * N1];     // 64 MB  half u (GEMM1 out, scan in-place, GEMM2 A)
__device__ __align__(1024) __half g_wih[(size_t)N1 * K1];       // 1 MB   half Wi
__device__ __align__(1024) __half g_wo2h[(size_t)N2 * K2];      // 1 MB   half permuted Wo
__device__ __align__(1024) float  g_carry[(size_t)B_DIM * NCHUNK * D_DIM * 2];

// ---------------------------------------------------------------------------
// fp16 TN GEMM: C[M,N] = A[M,K] * W[N,K]^T + bias (optional ReLU), fp32 accum.
// Block 128x128, BK=32 halves, 128 threads = 4 warps (2x2), warp tile 64x64.
// ldmatrix.x4 loads, 5-stage cp.async.cg (L1-bypass) pipeline, SSTH=40 pad,
// 2 CTAs/SM.
// ---------------------------------------------------------------------------
#define BMh 128
#define BNh 128
#define BKh 32
#define NSTG 5
#define SSTH 40                     // halves per smem row (32 + 8 pad)
#define STAGE_HALVES (BMh * SSTH)   // per matrix per stage = 5120 halves
#define GEMM_SMEM (2 * NSTG * STAGE_HALVES * 2)  // A+B, 5 stages = 102400 B

__device__ __forceinline__ void mma_f16(float* c, const uint32_t* a, const uint32_t* b) {
    asm volatile(
        "mma.sync.aligned.m16n8k16.row.col.f32.f16.f16.f32 "
        "{%0,%1,%2,%3},{%4,%5,%6,%7},{%8,%9},{%0,%1,%2,%3};\n"
        : "+f"(c[0]), "+f"(c[1]), "+f"(c[2]), "+f"(c[3])
        : "r"(a[0]), "r"(a[1]), "r"(a[2]), "r"(a[3]), "r"(b[0]), "r"(b[1]));
}

__device__ __forceinline__ void ldsm_x4(uint32_t& r0, uint32_t& r1,
                                        uint32_t& r2, uint32_t& r3, uint32_t addr) {
    asm volatile("ldmatrix.sync.aligned.m8n8.x4.shared.b16 {%0,%1,%2,%3}, [%4];"
        : "=r"(r0), "=r"(r1), "=r"(r2), "=r"(r3) : "r"(addr));
}

// one stage of cp.async.cg loads: A[128 x 32h] + B[128 x 32h], 128 threads
__device__ __forceinline__ void ld_stage(uint32_t sA, uint32_t sB,
                                         const __half* gA, const __half* gB,
                                         int K, int tid)
{
#pragma unroll
    for (int i = 0; i < 4; i++) {
        const int c = tid + 128 * i;          // 0..511 chunk of 8 halves
        const int row  = c >> 2;
        const int col8 = (c & 3) * 8;
        const uint32_t so = (uint32_t)(row * SSTH + col8) * 2u;
        asm volatile("cp.async.cg.shared.global [%0], [%1], 16;\n"
                     ::"r"(sA + so), "l"(gA + (size_t)row * K + col8));
        asm volatile("cp.async.cg.shared.global [%0], [%1], 16;\n"
                     ::"r"(sB + so), "l"(gB + (size_t)row * K + col8));
    }
    asm volatile("cp.async.commit_group;\n");
}

template <bool RELU, typename OutT>
__global__ void __launch_bounds__(128, 2)
gemm_h(const __half* __restrict__ A, const __half* __restrict__ W,
       const float* __restrict__ bias, OutT* __restrict__ C,
       int N, int K)
{
    extern __shared__ __align__(16) __half smem[];
    __half* As = smem;                          // [NSTG][128*SSTH]
    __half* Bs = smem + NSTG * STAGE_HALVES;    // [NSTG][128*SSTH]

    const int tid  = threadIdx.x;
    const int warp = tid >> 5;
    const int lane = tid & 31;
    const int g    = lane >> 2;   // 0..7
    const int tig  = lane & 3;    // 0..3
    const int wm   = warp >> 1;   // 0..1 -> m offset wm*64
    const int wn   = warp & 1;    // 0..1 -> n offset wn*64

    const int bm0 = blockIdx.y * BMh;
    const int bn0 = blockIdx.x * BNh;

    const __half* gA = A + (size_t)bm0 * K;
    const __half* gB = W + (size_t)bn0 * K;

    const uint32_t sA0 = (uint32_t)__cvta_generic_to_shared(As);
    const uint32_t sB0 = (uint32_t)__cvta_generic_to_shared(Bs);
    const uint32_t bufB = (uint32_t)STAGE_HALVES * 2u;  // bytes per stage

    // ldmatrix per-lane row/col (in halves)
    const int a_r  = (lane & 15);
    const int a_c8 = (lane >> 4) << 3;
    const int b_r  = ((lane >> 4) << 3) + (lane & 7);
    const int b_c8 = ((lane >> 3) & 1) << 3;

    float acc[4][8][4];
#pragma unroll
    for (int mt = 0; mt < 4; mt++)
#pragma unroll
        for (int nt = 0; nt < 8; nt++)
#pragma unroll
            for (int i = 0; i < 4; i++) acc[mt][nt][i] = 0.f;

    const int KT = K / BKh;

    // prologue: stages 0..NSTG-2
#pragma unroll
    for (int s = 0; s < NSTG - 1; s++)
        ld_stage(sA0 + s * bufB, sB0 + s * bufB,
                 gA + (size_t)s * BKh, gB + (size_t)s * BKh, K, tid);

#pragma unroll 1
    for (int kt = 0; kt < KT; kt++) {
        const int rem = KT - kt - 1;   // tiles after this one
        if (rem >= 3)      asm volatile("cp.async.wait_group 3;\n");
        else if (rem == 2) asm volatile("cp.async.wait_group 2;\n");
        else if (rem == 1) asm volatile("cp.async.wait_group 1;\n");
        else               asm volatile("cp.async.wait_group 0;\n");
        __syncthreads();
        // Single barrier per iteration: proves all warps consumed buf
        // (kt-1)%NSTG, which is exactly what the prefetch below (into buf
        // (kt+NSTG-1)%NSTG == (kt-1)%NSTG) overwrites.

        if (kt + NSTG - 1 < KT) {
            const uint32_t bo = (uint32_t)((kt + NSTG - 1) % NSTG) * bufB;
            ld_stage(sA0 + bo, sB0 + bo, gA + (size_t)(kt + NSTG - 1) * BKh,
                     gB + (size_t)(kt + NSTG - 1) * BKh, K, tid);
        }

        const uint32_t sa = sA0 + (uint32_t)(kt % NSTG) * bufB;
        const uint32_t sb = sB0 + (uint32_t)(kt % NSTG) * bufB;

#pragma unroll
        for (int ks = 0; ks < 2; ks++) {
            const int k0 = ks * 16;
            uint32_t af[4][4], bf[8][2];
#pragma unroll
            for (int mt = 0; mt < 4; mt++) {
                const int r = wm * 64 + mt * 16 + a_r;
                ldsm_x4(af[mt][0], af[mt][1], af[mt][2], af[mt][3],
                        sa + (uint32_t)(r * SSTH + a_c8 + k0) * 2u);
            }
#pragma unroll
            for (int ntp = 0; ntp < 4; ntp++) {
                const int r = wn * 64 + ntp * 16 + b_r;
                ldsm_x4(bf[2 * ntp][0], bf[2 * ntp][1],
                        bf[2 * ntp + 1][0], bf[2 * ntp + 1][1],
                        sb + (uint32_t)(r * SSTH + b_c8 + k0) * 2u);
            }
#pragma unroll
            for (int mt = 0; mt < 4; mt++)
#pragma unroll
                for (int nt = 0; nt < 8; nt++)
                    mma_f16(acc[mt][nt], af[mt], bf[nt]);
        }
    }

    // epilogue: bias (+ ReLU); fp32 or fp16 stores depending on OutT
#pragma unroll
    for (int mt = 0; mt < 4; mt++) {
#pragma unroll
        for (int nt = 0; nt < 8; nt++) {
            const int row = bm0 + wm * 64 + mt * 16 + g;
            const int col = bn0 + wn * 64 + nt * 8 + tig * 2;
            const float b0 = bias[col];
            const float b1 = bias[col + 1];
            float2 v0, v1;
            v0.x = acc[mt][nt][0] + b0; v0.y = acc[mt][nt][1] + b1;
            v1.x = acc[mt][nt][2] + b0; v1.y = acc[mt][nt][3] + b1;
            if (RELU) {
                v0.x = fmaxf(v0.x, 0.f); v0.y = fmaxf(v0.y, 0.f);
                v1.x = fmaxf(v1.x, 0.f); v1.y = fmaxf(v1.y, 0.f);
            }
            if (sizeof(OutT) == 2) {
                __half* Ch = (__half*)C;
                *(__half2*)&Ch[(size_t)row * N + col] = __floats2half2_rn(v0.x, v0.y);
                *(__half2*)&Ch[(size_t)(row + 8) * N + col] = __floats2half2_rn(v1.x, v1.y);
            } else {
                float* Cf = (float*)C;
                *(float2*)&Cf[(size_t)row * N + col] = v0;
                *(float2*)&Cf[(size_t)(row + 8) * N + col] = v1;
            }
        }
    }
}

// ---------------------------------------------------------------------------
// Scan: h_t = lambda_d * h_{t-1} + x_t (complex), chunked, recompute scheme.
// u layout: [B, L, D] of half2 (re, im) interleaved, scanned IN PLACE.
// Pass 1: per-chunk local scan -> carry only (no u writes).
// Pass 2: recompute local scan + carry-prefix correction + gamma -> write u.
// u (64MB) stays L2-resident across the passes.
// ---------------------------------------------------------------------------
__global__ void __launch_bounds__(256)
scan_carry(const __half* __restrict__ u, const float* __restrict__ pl,
           float* __restrict__ carry)
{
    const int idx = blockIdx.x * blockDim.x + threadIdx.x;  // B*NCHUNK*D
    const int d = idx % D_DIM;
    const int c = (idx / D_DIM) % NCHUNK;
    const int b = idx / (D_DIM * NCHUNK);

    const float v  = expf(pl[d]);
    const float th = expf(pl[D_DIM + d]);
    const float mg = expf(-v);
    const float2 lam = make_float2(mg * cosf(th), mg * sinf(th));

    const __half2* u2 = (const __half2*)u;
    size_t off = (size_t)(b * L_DIM + c * CHUNK) * D_DIM + d;

    float2 h = make_float2(0.f, 0.f);
#pragma unroll 4
    for (int t = 0; t < CHUNK; t++) {
        const float2 x = __half22float2(u2[off]);
        float2 nh;
        nh.x = fmaf(lam.x, h.x, fmaf(-lam.y, h.y, x.x));
        nh.y = fmaf(lam.x, h.y, fmaf(lam.y, h.x, x.y));
        h = nh;
        off += D_DIM;
    }
    ((float2*)carry)[(size_t)(b * NCHUNK + c) * D_DIM + d] = h;
}

__global__ void __launch_bounds__(256)
scan_apply(__half* __restrict__ u, const float* __restrict__ pl,
           const float* __restrict__ carry)
{
    const int idx = blockIdx.x * blockDim.x + threadIdx.x;  // B*NCHUNK*D
    const int d = idx % D_DIM;
    const int c = (idx / D_DIM) % NCHUNK;
    const int b = idx / (D_DIM * NCHUNK);

    const float v  = expf(pl[d]);
    const float th = expf(pl[D_DIM + d]);
    const float gamma = expf(pl[2 * D_DIM + d]);
    const float mg = expf(-v);
    const float2 lam = make_float2(mg * cosf(th), mg * sinf(th));

    // lambda^CHUNK via double trig (large angle; fast-math safe in double)
    const double ang = (double)th * (double)CHUNK;
    const float mgT = expf(-v * (float)CHUNK);
    const float2 lamT = make_float2(mgT * (float)cos(ang), mgT * (float)sin(ang));

    // exclusive prefix of chunk carries: E = sum_{j<c} lamT^{c-1-j} * carry_j
    const float2* c2 = (const float2*)carry;
    float2 E = make_float2(0.f, 0.f);
    for (int j = 0; j < c; j++) {
        const float2 cj = c2[(size_t)(b * NCHUNK + j) * D_DIM + d];
        float2 nE;
        nE.x = fmaf(lamT.x, E.x, fmaf(-lamT.y, E.y, cj.x));
        nE.y = fmaf(lamT.x, E.y, fmaf(lamT.y, E.x, cj.y));
        E = nE;
    }

    __half2* u2 = (__half2*)u;
    size_t off = (size_t)(b * L_DIM + c * CHUNK) * D_DIM + d;

    float2 h = make_float2(0.f, 0.f);   // local scan, recomputed
    float2 f = lam;                     // lambda^(t+1), iterated
#pragma unroll 4
    for (int t = 0; t < CHUNK; t++) {
        const float2 x = __half22float2(u2[off]);
        float2 nh;
        nh.x = fmaf(lam.x, h.x, fmaf(-lam.y, h.y, x.x));
        nh.y = fmaf(lam.x, h.y, fmaf(lam.y, h.x, x.y));
        h = nh;
        const float hr = (h.x + f.x * E.x - f.y * E.y) * gamma;
        const float hi = (h.y + f.x * E.y + f.y * E.x) * gamma;
        u2[off] = __floats2half2_rn(hr, hi);
        float2 nf;
        nf.x = f.x * lam.x - f.y * lam.y;
        nf.y = f.x * lam.y + f.y * lam.x;
        f = nf;
        off += D_DIM;
    }
}

// ---------------------------------------------------------------------------
// Fused prep: inputs f32->f16, Wi f32->f16, Wo permute+cvt. One launch.
// Block ranges: [0,8192) inputs, [8192,8448) Wi, [8448,9472) Wo permute.
// ---------------------------------------------------------------------------
#define PREP_IN_BLKS 8192   // M*K1/8/256
#define PREP_WI_BLKS 256    // N1*K1/8/256
#define PREP_WO_BLKS 1024   // N2*D/256
#define PREP_BLOCKS (PREP_IN_BLKS + PREP_WI_BLKS + PREP_WO_BLKS)

__device__ __forceinline__ void cvt8(const float* __restrict__ src,
                                     __half* __restrict__ dst, size_t i)
{
    const float4 a = *(const float4*)(src + i);
    const float4 b = *(const float4*)(src + i + 4);
    __half2 h[4];
    h[0] = __floats2half2_rn(a.x, a.y);
    h[1] = __floats2half2_rn(a.z, a.w);
    h[2] = __floats2half2_rn(b.x, b.y);
    h[3] = __floats2half2_rn(b.z, b.w);
    *(uint4*)(dst + i) = *(const uint4*)h;
}

__global__ void __launch_bounds__(256)
prep_all(const float* __restrict__ inputs, const float* __restrict__ Wi,
         const float* __restrict__ Wo,
         __half* __restrict__ inh, __half* __restrict__ wih,
         __half* __restrict__ wo2h)
{
    const int bid = blockIdx.x;
    if (bid < PREP_IN_BLKS) {
        const size_t i = ((size_t)bid * 256 + threadIdx.x) * 8;
        cvt8(inputs, inh, i);
    } else if (bid < PREP_IN_BLKS + PREP_WI_BLKS) {
        const size_t i = ((size_t)(bid - PREP_IN_BLKS) * 256 + threadIdx.x) * 8;
        cvt8(Wi, wih, i);
    } else {
        const int idx = (bid - PREP_IN_BLKS - PREP_WI_BLKS) * 256 + threadIdx.x;
        const int d = idx % D_DIM;
        const int n = idx / D_DIM;
        const float a = Wo[(size_t)n * K2 + d];
        const float b = Wo[(size_t)n * K2 + D_DIM + d];
        ((__half2*)wo2h)[(size_t)n * D_DIM + d] = __floats2half2_rn(a, b);
    }
}

// ---------------------------------------------------------------------------
extern "C" void kernel_launch(void* const* d_in, const int* in_sizes, int n_in,
                              void* d_out, int out_size)
{
    (void)in_sizes; (void)n_in; (void)out_size;
    const float* inputs = (const float*)d_in[0];
    const float* Wi     = (const float*)d_in[1];
    const float* bi     = (const float*)d_in[2];
    const float* Wo     = (const float*)d_in[3];
    const float* bo     = (const float*)d_in[4];
    const float* pl     = (const float*)d_in[5];
    float* out = (float*)d_out;

    float* carry;
    __half *inh, *uh, *wih, *wo2h;
    cudaGetSymbolAddress((void**)&carry, g_carry);
    cudaGetSymbolAddress((void**)&inh, g_inh);
    cudaGetSymbolAddress((void**)&uh, g_uh);
    cudaGetSymbolAddress((void**)&wih, g_wih);
    cudaGetSymbolAddress((void**)&wo2h, g_wo2h);

    cudaFuncSetAttribute(gemm_h<false, __half>,
                         cudaFuncAttributeMaxDynamicSharedMemorySize, GEMM_SMEM);
    cudaFuncSetAttribute(gemm_h<true, float>,
                         cudaFuncAttributeMaxDynamicSharedMemorySize, GEMM_SMEM);

    // fused prep: inputs + Wi -> half, Wo -> permuted half
    prep_all<<<PREP_BLOCKS, 256>>>(inputs, Wi, Wo, inh, wih, wo2h);

    // GEMM1: uh = half(inputs @ Wi^T + bi)
    {
        dim3 grid(N1 / BNh, M_DIM / BMh);
        gemm_h<false, __half><<<grid, 128, GEMM_SMEM>>>(inh, wih, bi, uh, N1, K1);
    }

    // chunked complex scan over uh (in place): carries, then recompute+apply
    scan_carry<<<(B_DIM * NCHUNK * D_DIM) / 256, 256>>>(uh, pl, carry);
    scan_apply<<<(B_DIM * NCHUNK * D_DIM) / 256, 256>>>(uh, pl, carry);

    // GEMM2: out = relu(uh @ Wo2^T + bo)
    {
        dim3 grid(N2 / BNh, M_DIM / BMh);
        gemm_h<true, float><<<grid, 128, GEMM_SMEM>>>(uh, wo2h, bo, out, N2, K2);
    }
}

// round 17
// speedup vs baseline: 1.1011x; 1.1011x over previous
#include <cuda_runtime.h>
#include <cuda_fp16.h>
#include <cstdint>
#include <cmath>

// ---------------------------------------------------------------------------
// Problem dims (fixed)
#define B_DIM 8
#define L_DIM 4096
#define D_DIM 512
#define M_DIM (B_DIM * L_DIM)   // 32768
#define N1 (2 * D_DIM)          // 1024
#define K1 (D_DIM)              // 512
#define N2 (D_DIM)              // 512
#define K2 (2 * D_DIM)          // 1024

#define CHUNK 64
#define NCHUNK (L_DIM / CHUNK)  // 64

// Scratch (device globals; allocation is banned)
__device__ __align__(1024) __half g_inh[(size_t)M_DIM * K1];    // 32 MB  half inputs
__device__ __align__(1024) __half g_uh[(size_t)M_DIM * N1];     // 64 MB  half u (GEMM1 out, scan in-place, GEMM2 A)
__device__ __align__(1024) __half g_wih[(size_t)N1 * K1];       // 1 MB   half Wi
__device__ __align__(1024) __half g_wo2h[(size_t)N2 * K2];      // 1 MB   half permuted Wo
__device__ __align__(1024) float  g_carry[(size_t)B_DIM * NCHUNK * D_DIM * 2];  // 2 MB

// ---------------------------------------------------------------------------
// fp16 TN GEMM: C[M,N] = A[M,K] * W[N,K]^T + bias (optional ReLU), fp32 accum.
// Block 128x128, BK=32 halves, 128 threads = 4 warps (2x2), warp tile 64x64.
// ldmatrix.x4 loads, 4-stage cp.async.ca pipeline, SSTH=40 pad, 2 CTAs/SM.
// (Round-14 proven config — do not touch.)
// ---------------------------------------------------------------------------
#define BMh 128
#define BNh 128
#define BKh 32
#define NSTG 4
#define SSTH 40                     // halves per smem row (32 + 8 pad)
#define STAGE_HALVES (BMh * SSTH)   // per matrix per stage = 5120 halves
#define GEMM_SMEM (2 * NSTG * STAGE_HALVES * 2)  // A+B, 4 stages = 81920 B

__device__ __forceinline__ void mma_f16(float* c, const uint32_t* a, const uint32_t* b) {
    asm volatile(
        "mma.sync.aligned.m16n8k16.row.col.f32.f16.f16.f32 "
        "{%0,%1,%2,%3},{%4,%5,%6,%7},{%8,%9},{%0,%1,%2,%3};\n"
        : "+f"(c[0]), "+f"(c[1]), "+f"(c[2]), "+f"(c[3])
        : "r"(a[0]), "r"(a[1]), "r"(a[2]), "r"(a[3]), "r"(b[0]), "r"(b[1]));
}

__device__ __forceinline__ void ldsm_x4(uint32_t& r0, uint32_t& r1,
                                        uint32_t& r2, uint32_t& r3, uint32_t addr) {
    asm volatile("ldmatrix.sync.aligned.m8n8.x4.shared.b16 {%0,%1,%2,%3}, [%4];"
        : "=r"(r0), "=r"(r1), "=r"(r2), "=r"(r3) : "r"(addr));
}

// one stage of cp.async loads: A[128 x 32h] + B[128 x 32h], 128 threads
__device__ __forceinline__ void ld_stage(uint32_t sA, uint32_t sB,
                                         const __half* gA, const __half* gB,
                                         int K, int tid)
{
#pragma unroll
    for (int i = 0; i < 4; i++) {
        const int c = tid + 128 * i;          // 0..511 chunk of 8 halves
        const int row  = c >> 2;
        const int col8 = (c & 3) * 8;
        const uint32_t so = (uint32_t)(row * SSTH + col8) * 2u;
        asm volatile("cp.async.ca.shared.global [%0], [%1], 16;\n"
                     ::"r"(sA + so), "l"(gA + (size_t)row * K + col8));
        asm volatile("cp.async.ca.shared.global [%0], [%1], 16;\n"
                     ::"r"(sB + so), "l"(gB + (size_t)row * K + col8));
    }
    asm volatile("cp.async.commit_group;\n");
}

template <bool RELU, typename OutT>
__global__ void __launch_bounds__(128, 2)
gemm_h(const __half* __restrict__ A, const __half* __restrict__ W,
       const float* __restrict__ bias, OutT* __restrict__ C,
       int N, int K)
{
    extern __shared__ __align__(16) __half smem[];
    __half* As = smem;                          // [NSTG][128*SSTH]
    __half* Bs = smem + NSTG * STAGE_HALVES;    // [NSTG][128*SSTH]

    const int tid  = threadIdx.x;
    const int warp = tid >> 5;
    const int lane = tid & 31;
    const int g    = lane >> 2;   // 0..7
    const int tig  = lane & 3;    // 0..3
    const int wm   = warp >> 1;   // 0..1 -> m offset wm*64
    const int wn   = warp & 1;    // 0..1 -> n offset wn*64

    const int bm0 = blockIdx.y * BMh;
    const int bn0 = blockIdx.x * BNh;

    const __half* gA = A + (size_t)bm0 * K;
    const __half* gB = W + (size_t)bn0 * K;

    const uint32_t sA0 = (uint32_t)__cvta_generic_to_shared(As);
    const uint32_t sB0 = (uint32_t)__cvta_generic_to_shared(Bs);
    const uint32_t bufB = (uint32_t)STAGE_HALVES * 2u;  // bytes per stage

    // ldmatrix per-lane row/col (in halves)
    const int a_r  = (lane & 15);
    const int a_c8 = (lane >> 4) << 3;
    const int b_r  = ((lane >> 4) << 3) + (lane & 7);
    const int b_c8 = ((lane >> 3) & 1) << 3;

    float acc[4][8][4];
#pragma unroll
    for (int mt = 0; mt < 4; mt++)
#pragma unroll
        for (int nt = 0; nt < 8; nt++)
#pragma unroll
            for (int i = 0; i < 4; i++) acc[mt][nt][i] = 0.f;

    const int KT = K / BKh;

    // prologue: stages 0,1,2
    ld_stage(sA0, sB0, gA, gB, K, tid);
    ld_stage(sA0 + bufB, sB0 + bufB, gA + BKh, gB + BKh, K, tid);
    ld_stage(sA0 + 2 * bufB, sB0 + 2 * bufB, gA + 2 * BKh, gB + 2 * BKh, K, tid);

#pragma unroll 1
    for (int kt = 0; kt < KT; kt++) {
        if (kt + 2 < KT)      asm volatile("cp.async.wait_group 2;\n");
        else if (kt + 1 < KT) asm volatile("cp.async.wait_group 1;\n");
        else                  asm volatile("cp.async.wait_group 0;\n");
        __syncthreads();
        // Single barrier per iteration: proves all warps consumed buf
        // (kt-1)%4, which is exactly what the prefetch below (into buf
        // (kt+3)%4 == (kt-1)%4) overwrites.

        if (kt + 3 < KT) {
            const uint32_t bo = (uint32_t)((kt + 3) % NSTG) * bufB;
            ld_stage(sA0 + bo, sB0 + bo, gA + (size_t)(kt + 3) * BKh,
                     gB + (size_t)(kt + 3) * BKh, K, tid);
        }

        const uint32_t sa = sA0 + (uint32_t)(kt % NSTG) * bufB;
        const uint32_t sb = sB0 + (uint32_t)(kt % NSTG) * bufB;

#pragma unroll
        for (int ks = 0; ks < 2; ks++) {
            const int k0 = ks * 16;
            uint32_t af[4][4], bf[8][2];
#pragma unroll
            for (int mt = 0; mt < 4; mt++) {
                const int r = wm * 64 + mt * 16 + a_r;
                ldsm_x4(af[mt][0], af[mt][1], af[mt][2], af[mt][3],
                        sa + (uint32_t)(r * SSTH + a_c8 + k0) * 2u);
            }
#pragma unroll
            for (int ntp = 0; ntp < 4; ntp++) {
                const int r = wn * 64 + ntp * 16 + b_r;
                ldsm_x4(bf[2 * ntp][0], bf[2 * ntp][1],
                        bf[2 * ntp + 1][0], bf[2 * ntp + 1][1],
                        sb + (uint32_t)(r * SSTH + b_c8 + k0) * 2u);
            }
#pragma unroll
            for (int mt = 0; mt < 4; mt++)
#pragma unroll
                for (int nt = 0; nt < 8; nt++)
                    mma_f16(acc[mt][nt], af[mt], bf[nt]);
        }
    }

    // epilogue: bias (+ ReLU); fp32 or fp16 stores depending on OutT
#pragma unroll
    for (int mt = 0; mt < 4; mt++) {
#pragma unroll
        for (int nt = 0; nt < 8; nt++) {
            const int row = bm0 + wm * 64 + mt * 16 + g;
            const int col = bn0 + wn * 64 + nt * 8 + tig * 2;
            const float b0 = bias[col];
            const float b1 = bias[col + 1];
            float2 v0, v1;
            v0.x = acc[mt][nt][0] + b0; v0.y = acc[mt][nt][1] + b1;
            v1.x = acc[mt][nt][2] + b0; v1.y = acc[mt][nt][3] + b1;
            if (RELU) {
                v0.x = fmaxf(v0.x, 0.f); v0.y = fmaxf(v0.y, 0.f);
                v1.x = fmaxf(v1.x, 0.f); v1.y = fmaxf(v1.y, 0.f);
            }
            if (sizeof(OutT) == 2) {
                __half* Ch = (__half*)C;
                *(__half2*)&Ch[(size_t)row * N + col] = __floats2half2_rn(v0.x, v0.y);
                *(__half2*)&Ch[(size_t)(row + 8) * N + col] = __floats2half2_rn(v1.x, v1.y);
            } else {
                float* Cf = (float*)C;
                *(float2*)&Cf[(size_t)row * N + col] = v0;
                *(float2*)&Cf[(size_t)(row + 8) * N + col] = v1;
            }
        }
    }
}

// ---------------------------------------------------------------------------
// Scan: h_t = lambda_d * h_{t-1} + x_t (complex), chunked, recompute scheme.
// u layout: [B, L, D] of half2 (re, im) interleaved, scanned IN PLACE.
// CHUNK=64 -> 262144 threads -> ~7 CTAs/SM: latency fully hidden, BW-bound.
// Pass 1: per-chunk local scan -> carry only (no u writes).
// Pass 2: recompute local scan + carry-prefix correction + gamma -> write u.
// ---------------------------------------------------------------------------
__global__ void __launch_bounds__(256)
scan_carry(const __half* __restrict__ u, const float* __restrict__ pl,
           float* __restrict__ carry)
{
    const int idx = blockIdx.x * blockDim.x + threadIdx.x;  // B*NCHUNK*D
    const int d = idx % D_DIM;
    const int c = (idx / D_DIM) % NCHUNK;
    const int b = idx / (D_DIM * NCHUNK);

    const float v  = expf(pl[d]);
    const float th = expf(pl[D_DIM + d]);
    const float mg = expf(-v);
    const float2 lam = make_float2(mg * cosf(th), mg * sinf(th));

    const __half2* u2 = (const __half2*)u;
    size_t off = (size_t)(b * L_DIM + c * CHUNK) * D_DIM + d;

    float2 h = make_float2(0.f, 0.f);
#pragma unroll 4
    for (int t = 0; t < CHUNK; t++) {
        const float2 x = __half22float2(u2[off]);
        float2 nh;
        nh.x = fmaf(lam.x, h.x, fmaf(-lam.y, h.y, x.x));
        nh.y = fmaf(lam.x, h.y, fmaf(lam.y, h.x, x.y));
        h = nh;
        off += D_DIM;
    }
    ((float2*)carry)[(size_t)(b * NCHUNK + c) * D_DIM + d] = h;
}

__global__ void __launch_bounds__(256)
scan_apply(__half* __restrict__ u, const float* __restrict__ pl,
           const float* __restrict__ carry)
{
    const int idx = blockIdx.x * blockDim.x + threadIdx.x;  // B*NCHUNK*D
    const int d = idx % D_DIM;
    const int c = (idx / D_DIM) % NCHUNK;
    const int b = idx / (D_DIM * NCHUNK);

    const float v  = expf(pl[d]);
    const float th = expf(pl[D_DIM + d]);
    const float gamma = expf(pl[2 * D_DIM + d]);
    const float mg = expf(-v);
    const float2 lam = make_float2(mg * cosf(th), mg * sinf(th));

    // lambda^CHUNK via double trig (large angle; fast-math safe in double)
    const double ang = (double)th * (double)CHUNK;
    const float mgT = expf(-v * (float)CHUNK);
    const float2 lamT = make_float2(mgT * (float)cos(ang), mgT * (float)sin(ang));

    // exclusive prefix of chunk carries: E = sum_{j<c} lamT^{c-1-j} * carry_j
    const float2* c2 = (const float2*)carry;
    float2 E = make_float2(0.f, 0.f);
    for (int j = 0; j < c; j++) {
        const float2 cj = c2[(size_t)(b * NCHUNK + j) * D_DIM + d];
        float2 nE;
        nE.x = fmaf(lamT.x, E.x, fmaf(-lamT.y, E.y, cj.x));
        nE.y = fmaf(lamT.x, E.y, fmaf(lamT.y, E.x, cj.y));
        E = nE;
    }

    __half2* u2 = (__half2*)u;
    size_t off = (size_t)(b * L_DIM + c * CHUNK) * D_DIM + d;

    float2 h = make_float2(0.f, 0.f);   // local scan, recomputed
    float2 f = lam;                     // lambda^(t+1), iterated
#pragma unroll 4
    for (int t = 0; t < CHUNK; t++) {
        const float2 x = __half22float2(u2[off]);
        float2 nh;
        nh.x = fmaf(lam.x, h.x, fmaf(-lam.y, h.y, x.x));
        nh.y = fmaf(lam.x, h.y, fmaf(lam.y, h.x, x.y));
        h = nh;
        const float hr = (h.x + f.x * E.x - f.y * E.y) * gamma;
        const float hi = (h.y + f.x * E.y + f.y * E.x) * gamma;
        u2[off] = __floats2half2_rn(hr, hi);
        float2 nf;
        nf.x = f.x * lam.x - f.y * lam.y;
        nf.y = f.x * lam.y + f.y * lam.x;
        f = nf;
        off += D_DIM;
    }
}

// ---------------------------------------------------------------------------
// Fused prep: inputs f32->f16, Wi f32->f16, Wo permute+cvt. One launch.
// ---------------------------------------------------------------------------
#define PREP_IN_BLKS 8192   // M*K1/8/256
#define PREP_WI_BLKS 256    // N1*K1/8/256
#define PREP_WO_BLKS 1024   // N2*D/256
#define PREP_BLOCKS (PREP_IN_BLKS + PREP_WI_BLKS + PREP_WO_BLKS)

__device__ __forceinline__ void cvt8(const float* __restrict__ src,
                                     __half* __restrict__ dst, size_t i)
{
    const float4 a = *(const float4*)(src + i);
    const float4 b = *(const float4*)(src + i + 4);
    __half2 h[4];
    h[0] = __floats2half2_rn(a.x, a.y);
    h[1] = __floats2half2_rn(a.z, a.w);
    h[2] = __floats2half2_rn(b.x, b.y);
    h[3] = __floats2half2_rn(b.z, b.w);
    *(uint4*)(dst + i) = *(const uint4*)h;
}

__global__ void __launch_bounds__(256)
prep_all(const float* __restrict__ inputs, const float* __restrict__ Wi,
         const float* __restrict__ Wo,
         __half* __restrict__ inh, __half* __restrict__ wih,
         __half* __restrict__ wo2h)
{
    const int bid = blockIdx.x;
    if (bid < PREP_IN_BLKS) {
        const size_t i = ((size_t)bid * 256 + threadIdx.x) * 8;
        cvt8(inputs, inh, i);
    } else if (bid < PREP_IN_BLKS + PREP_WI_BLKS) {
        const size_t i = ((size_t)(bid - PREP_IN_BLKS) * 256 + threadIdx.x) * 8;
        cvt8(Wi, wih, i);
    } else {
        const int idx = (bid - PREP_IN_BLKS - PREP_WI_BLKS) * 256 + threadIdx.x;
        const int d = idx % D_DIM;
        const int n = idx / D_DIM;
        const float a = Wo[(size_t)n * K2 + d];
        const float b = Wo[(size_t)n * K2 + D_DIM + d];
        ((__half2*)wo2h)[(size_t)n * D_DIM + d] = __floats2half2_rn(a, b);
    }
}

// ---------------------------------------------------------------------------
extern "C" void kernel_launch(void* const* d_in, const int* in_sizes, int n_in,
                              void* d_out, int out_size)
{
    (void)in_sizes; (void)n_in; (void)out_size;
    const float* inputs = (const float*)d_in[0];
    const float* Wi     = (const float*)d_in[1];
    const float* bi     = (const float*)d_in[2];
    const float* Wo     = (const float*)d_in[3];
    const float* bo     = (const float*)d_in[4];
    const float* pl     = (const float*)d_in[5];
    float* out = (float*)d_out;

    float* carry;
    __half *inh, *uh, *wih, *wo2h;
    cudaGetSymbolAddress((void**)&carry, g_carry);
    cudaGetSymbolAddress((void**)&inh, g_inh);
    cudaGetSymbolAddress((void**)&uh, g_uh);
    cudaGetSymbolAddress((void**)&wih, g_wih);
    cudaGetSymbolAddress((void**)&wo2h, g_wo2h);

    cudaFuncSetAttribute(gemm_h<false, __half>,
                         cudaFuncAttributeMaxDynamicSharedMemorySize, GEMM_SMEM);
    cudaFuncSetAttribute(gemm_h<true, float>,
                         cudaFuncAttributeMaxDynamicSharedMemorySize, GEMM_SMEM);

    // fused prep: inputs + Wi -> half, Wo -> permuted half
    prep_all<<<PREP_BLOCKS, 256>>>(inputs, Wi, Wo, inh, wih, wo2h);

    // GEMM1: uh = half(inputs @ Wi^T + bi)
    {
        dim3 grid(N1 / BNh, M_DIM / BMh);
        gemm_h<false, __half><<<grid, 128, GEMM_SMEM>>>(inh, wih, bi, uh, N1, K1);
    }

    // chunked complex scan over uh (in place): carries, then recompute+apply
    scan_carry<<<(B_DIM * NCHUNK * D_DIM) / 256, 256>>>(uh, pl, carry);
    scan_apply<<<(B_DIM * NCHUNK * D_DIM) / 256, 256>>>(uh, pl, carry);

    // GEMM2: out = relu(uh @ Wo2^T + bo)
    {
        dim3 grid(N2 / BNh, M_DIM / BMh);
        gemm_h<true, float><<<grid, 128, GEMM_SMEM>>>(uh, wo2h, bo, out, N2, K2);
    }
}